// round 8
// baseline (speedup 1.0000x reference)
#include <cuda_runtime.h>
#include <math.h>

// Problem constants
constexpr int BB   = 8;
constexpr int NCLS = 2;
constexpr int NSP  = 8;
constexpr int CH   = 64;
constexpr int HH   = 192;
constexpr int WW   = 192;
constexpr int HWSZ = HH * WW;   // 36864
constexpr int RPS  = 12;        // rows per strip in k_P (16 strips)

// k_P smem layout constants (x stored as duplicated f32x2 pairs)
constexpr int XCHUNK = 102;                // 50 used pairs (100 floats) + 2 pad floats
constexpr int XSLOT  = 4 * XCHUNK;         // 408 floats per row-slot
constexpr int XCP    = 3 * XSLOT;          // 1224 (even: 8B aligned; /2=612, 612%16=4)
constexpr int SPCOLSTRIDE = 18;
// spidx(col) = col*18 + 2*(col/48) + sc ; max 191*18+6+15 = 3459
constexpr int SPSZ = 3464;

typedef unsigned long long u64t;

// ---------------- device scratch ----------------
__device__ float g_space[BB * NCLS * NSP * HWSZ];   // [b][sc][hw]
__device__ float g_S[BB * NCLS * NSP];
__device__ float g_P[BB * NSP * NCLS * CH * 9];     // [b][s][c][c'][k]
__device__ float g_wT[CH * CH * 9];                 // [d][k][o]
__device__ float g_U[BB * NCLS * 9 * CH];           // [b][c][k][o]
__device__ float g_g[BB * NCLS * HWSZ];             // [b][c][hw]
__device__ float g_bnsum[CH];
__device__ float g_bnsq[CH];
__device__ float g_bna[CH];
__device__ float g_bnb[CH];

__device__ __forceinline__ float sigmoidf_(float x) {
    return 1.0f / (1.0f + __expf(-x));
}

// ---- packed f32x2 helpers ----
__device__ __forceinline__ u64t pack1(float v) {
    u64t r; asm("mov.b64 %0, {%1, %1};" : "=l"(r) : "f"(v)); return r;
}
__device__ __forceinline__ u64t ffma2(u64t a, u64t b, u64t c) {
    u64t d; asm("fma.rn.f32x2 %0, %1, %2, %3;" : "=l"(d) : "l"(a), "l"(b), "l"(c)); return d;
}
__device__ __forceinline__ float2 unpack2(u64t v) {
    float2 f; asm("mov.b64 {%0, %1}, %2;" : "=f"(f.x), "=f"(f.y) : "l"(v)); return f;
}

// ---------------- kernel: zero accumulators + transpose W_single ----------------
__global__ void k_init(const float* __restrict__ Ws) {
    int i = blockIdx.x * blockDim.x + threadIdx.x;
    if (i < BB * NSP * NCLS * CH * 9) g_P[i] = 0.f;
    if (i < CH) { g_bnsum[i] = 0.f; g_bnsq[i] = 0.f; }
    if (i < BB * NCLS * NSP) g_S[i] = 0.f;
    if (i < CH * CH * 9) {
        int o = i / 576;
        int rem = i % 576;
        int d = rem / 9;
        int k = rem % 9;
        g_wT[d * 576 + k * 64 + o] = Ws[i];
    }
}

// ---------------- kernel 1: space channels + spatial sums + g maps (merged) ----------------
// grid (144, 8), block 256. blockIdx.y = b. Each thread handles both classes at pixel p.
__global__ __launch_bounds__(256) void k_spaceg(const float* __restrict__ cs,
                                                const float* __restrict__ Wcsp,
                                                const float* __restrict__ Wcv,
                                                const float* __restrict__ Wa,
                                                const float* __restrict__ Wcomb) {
    __shared__ float s_q[8], s_wa[8];
    if (threadIdx.x < 8) {
        s_q[threadIdx.x] = Wcomb[threadIdx.x] * Wcv[threadIdx.x];
        s_wa[threadIdx.x] = Wa[threadIdx.x];
    }
    __syncthreads();

    int b = blockIdx.y;
    int p = blockIdx.x * 256 + threadIdx.x;       // 144*256 == HWSZ
    int h = p / WW, w = p % WW;

    float sums[2 * NSP];
#pragma unroll
    for (int c = 0; c < 2; c++) {
        const float* base = cs + (b * NCLS + c) * HWSZ;
        float n[9];
#pragma unroll
        for (int dy = 0; dy < 3; dy++) {
#pragma unroll
            for (int dx = 0; dx < 3; dx++) {
                int gh = h + dy - 1, gw = w + dx - 1;
                float v = 0.f;
                if (gh >= 0 && gh < HH && gw >= 0 && gw < WW)
                    v = sigmoidf_(base[gh * WW + gw]);
                n[dy * 3 + dx] = v;
            }
        }
        float ch0 = n[4];
        g_space[((b * NCLS + c) * NSP + 0) * HWSZ + p] = ch0;
        sums[c * NSP] = ch0;
#pragma unroll
        for (int j = 0; j < 7; j++) {
            float z = 0.f;
#pragma unroll
            for (int k = 0; k < 9; k++) z += Wcsp[j * 9 + k] * n[k];
            float v = sigmoidf_(z);
            g_space[((b * NCLS + c) * NSP + j + 1) * HWSZ + p] = v;
            sums[c * NSP + j + 1] = v;
        }
        // g map for this class (uses center prob = n[4])
        float gg = 0.f;
#pragma unroll
        for (int s = 0; s < 8; s++) gg += s_q[s] * sigmoidf_(s_wa[s] * n[4]);
        g_g[(b * NCLS + c) * HWSZ + p] = gg;
    }

#pragma unroll
    for (int sc = 0; sc < 16; sc++) {
        float v = sums[sc];
#pragma unroll
        for (int off = 16; off; off >>= 1)
            v += __shfl_down_sync(0xffffffffu, v, off);
        if ((threadIdx.x & 31) == 0) {
            int c = sc / NSP, s = sc % NSP;
            atomicAdd(&g_S[(b * NCLS + c) * NSP + s], v);
        }
    }
}

// ---------------- kernel 2: P correlation (dup-x f32x2, conflict-free) ----------------
// s_x holds x values duplicated as pairs: pair t of chunk j = (x[48j-1+t], same)
__device__ __forceinline__ void load_x_dup(float* s_x, const float* __restrict__ xb,
                                           int grow, int tid) {
    int slot = ((grow % 3) + 3) % 3;
    bool rok = (grow >= 0 && grow < HH);
    const float* rowp = xb + grow * WW;
#pragma unroll
    for (int m = 0; m < 13; m++) {
        int i = tid + m * 128;
        if (i < 1600) {
            int cp = i / 200;
            int rem = i - cp * 200;
            int j = rem / 50;
            int t = rem - j * 50;
            int col = 48 * j - 1 + t;
            float v = 0.f;
            if (rok && col >= 0 && col < WW) v = rowp[cp * HWSZ + col];
            *(u64t*)(s_x + cp * XCP + slot * XSLOT + j * XCHUNK + 2 * t) = pack1(v);
        }
    }
}

__global__ __launch_bounds__(128) void k_P(const float* __restrict__ x) {
    __shared__ __align__(16) float s_x[8 * XCP];      // 9792 floats = 39.2 KB
    __shared__ __align__(16) float s_spT[SPSZ];       // 13.9 KB

    int b = blockIdx.z, cgrp = blockIdx.y, strip = blockIdx.x;
    int r0 = strip * RPS;
    int tid = threadIdx.x;
    int scq = tid >> 5;          // warp id -> 4 sc (2 f32x2 pairs)
    int lane = tid & 31;
    int cpl = lane >> 2;         // 0..7 local c'
    int j = lane & 3;            // chunk 0..3 (48 cols each)
    int scb = scq * 4;

    u64t acc[2][9];
#pragma unroll
    for (int i = 0; i < 2; i++)
#pragma unroll
        for (int k = 0; k < 9; k++) acc[i][k] = 0ull;

    const float* xb = x + (size_t)(b * CH + cgrp * 8) * HWSZ;
    const float* spb = g_space + (size_t)b * 16 * HWSZ;

    load_x_dup(s_x, xb, r0 - 1, tid);
    load_x_dup(s_x, xb, r0, tid);

    const int xoff = cpl * XCP + j * XCHUNK;
    const int spoff = 866 * j + scb;   // (48j)*18 + 2j + scb

    // affine transpose-copy mapping
    int sc_c = tid >> 3;       // 0..15
    int t8 = tid & 7;          // 0..7
    const float* sp_src0 = spb + sc_c * HWSZ + t8;
    float* sp_dst = s_spT + t8 * 18 + sc_c;

    for (int r = r0; r < r0 + RPS; r++) {
        __syncthreads();
        load_x_dup(s_x, xb, r + 1, tid);
        {
            const float* srow = sp_src0 + r * WW;
#pragma unroll
            for (int m = 0; m < 24; m++) {
                sp_dst[144 * m + 2 * (m / 6)] = srow[8 * m];
            }
        }
        __syncthreads();

        int sm1 = (r + 2) % 3;
        int sm0 = r % 3;
        int sp1 = (r + 1) % 3;
        const float* xr0 = s_x + xoff + sm1 * XSLOT;
        const float* xr1 = s_x + xoff + sm0 * XSLOT;
        const float* xr2 = s_x + xoff + sp1 * XSLOT;

        u64t m0 = *(const u64t*)(xr0);       // x[col0-1] dup
        u64t m1 = *(const u64t*)(xr1);
        u64t m2 = *(const u64t*)(xr2);
        u64t c0 = *(const u64t*)(xr0 + 2);   // x[col0] dup
        u64t c1 = *(const u64t*)(xr1 + 2);
        u64t c2 = *(const u64t*)(xr2 + 2);
        const float* snp = s_spT + spoff;

#pragma unroll 4
        for (int cc = 0; cc < 48; cc++) {
            u64t p0 = *(const u64t*)(xr0 + 2 * (cc + 2));   // x[col+1] dup
            u64t p1 = *(const u64t*)(xr1 + 2 * (cc + 2));
            u64t p2 = *(const u64t*)(xr2 + 2 * (cc + 2));
            u64t snA = *(const u64t*)(snp);
            u64t snB = *(const u64t*)(snp + 2);

            acc[0][0] = ffma2(snA, m0, acc[0][0]);
            acc[0][1] = ffma2(snA, c0, acc[0][1]);
            acc[0][2] = ffma2(snA, p0, acc[0][2]);
            acc[0][3] = ffma2(snA, m1, acc[0][3]);
            acc[0][4] = ffma2(snA, c1, acc[0][4]);
            acc[0][5] = ffma2(snA, p1, acc[0][5]);
            acc[0][6] = ffma2(snA, m2, acc[0][6]);
            acc[0][7] = ffma2(snA, c2, acc[0][7]);
            acc[0][8] = ffma2(snA, p2, acc[0][8]);

            acc[1][0] = ffma2(snB, m0, acc[1][0]);
            acc[1][1] = ffma2(snB, c0, acc[1][1]);
            acc[1][2] = ffma2(snB, p0, acc[1][2]);
            acc[1][3] = ffma2(snB, m1, acc[1][3]);
            acc[1][4] = ffma2(snB, c1, acc[1][4]);
            acc[1][5] = ffma2(snB, p1, acc[1][5]);
            acc[1][6] = ffma2(snB, m2, acc[1][6]);
            acc[1][7] = ffma2(snB, c2, acc[1][7]);
            acc[1][8] = ffma2(snB, p2, acc[1][8]);

            m0 = c0; c0 = p0;
            m1 = c1; c1 = p1;
            m2 = c2; c2 = p2;
            snp += SPCOLSTRIDE;
        }
    }

    int cp = cgrp * 8 + cpl;
#pragma unroll
    for (int scp = 0; scp < 2; scp++) {
        int sc0 = scb + scp * 2;
        int sc1 = sc0 + 1;
        int sA = sc0 & 7, cA = sc0 >> 3;
        int sB = sc1 & 7, cB = sc1 >> 3;
        float* dA = &g_P[(((b * 8 + sA) * 2 + cA) * 64 + cp) * 9];
        float* dB = &g_P[(((b * 8 + sB) * 2 + cB) * 64 + cp) * 9];
#pragma unroll
        for (int k = 0; k < 9; k++) {
            float2 v = unpack2(acc[scp][k]);
            atomicAdd(&dA[k], v.x);
            atomicAdd(&dB[k], v.y);
        }
    }
}

// ---------------- kernel 3: tok2 + U (merged) ----------------
// grid 8 (b), block 256.
__global__ __launch_bounds__(256) void k_tokU(const float* __restrict__ Wx,
                                              const float* __restrict__ Wcs) {
    __shared__ float s_part[2][128];
    __shared__ float s_tok[128];
    int b = blockIdx.x;
    int tid = threadIdx.x;
    int cd = tid & 127;          // c*64+d
    int sh = tid >> 7;           // 0..1 (s-half)
    int c = cd >> 6, d = cd & 63;

    float acc = 0.f;
#pragma unroll
    for (int si = 0; si < 4; si++) {
        int s = sh * 4 + si;
        float inv = Wcs[s] / g_S[(b * NCLS + c) * NSP + s];
        const float4* row = (const float4*)(Wx + (s * CH + d) * 576);
        const float4* pp = (const float4*)(g_P + (((b * NSP + s) * NCLS + c) * CH) * 9);
        float dot = 0.f;
#pragma unroll 4
        for (int m = 0; m < 144; m++) {
            float4 wv = row[m];
            float4 pv = pp[m];
            dot += wv.x * pv.x + wv.y * pv.y + wv.z * pv.z + wv.w * pv.w;
        }
        acc += inv * dot;
    }
    s_part[sh][cd] = acc;
    __syncthreads();
    if (tid < 128) s_tok[tid] = s_part[0][tid] + s_part[1][tid];
    __syncthreads();

    // U[b][c][k][o] = sum_d wT[d][k][o] * tok[c][d]
    for (int idx = tid; idx < 1152; idx += 256) {
        int o = idx & 63;
        int ck = idx >> 6;           // 0..17
        int c2 = (ck >= 9) ? 1 : 0;
        int k = ck - c2 * 9;
        float a = 0.f;
#pragma unroll 8
        for (int dd = 0; dd < 64; dd++)
            a += g_wT[dd * 576 + k * 64 + o] * s_tok[c2 * 64 + dd];
        g_U[((b * 2 + c2) * 9 + k) * 64 + o] = a;
    }
}

// ---------------- shared tile-conv helper ----------------
__device__ __forceinline__ void conv_tile(const float s_g[2][10][19],
                                          const float s_U[2][9][64],
                                          int tid, float acc[4][8]) {
    int og = tid >> 4, pg = tid & 15;
    int row = pg >> 1, colb = (pg & 1) * 8;
    int o0 = og * 4;
#pragma unroll
    for (int oo = 0; oo < 4; oo++)
#pragma unroll
        for (int jj = 0; jj < 8; jj++) acc[oo][jj] = 0.f;
#pragma unroll
    for (int c = 0; c < 2; c++) {
#pragma unroll
        for (int ky = 0; ky < 3; ky++) {
            const float* vrow = &s_g[c][row + ky][colb];
            float v[10];
#pragma unroll
            for (int i = 0; i < 10; i++) v[i] = vrow[i];
#pragma unroll
            for (int kx = 0; kx < 3; kx++) {
                float4 wv = *(const float4*)&s_U[c][ky * 3 + kx][o0];
#pragma unroll
                for (int jj = 0; jj < 8; jj++) {
                    float vv = v[jj + kx];
                    acc[0][jj] += wv.x * vv;
                    acc[1][jj] += wv.y * vv;
                    acc[2][jj] += wv.z * vv;
                    acc[3][jj] += wv.w * vv;
                }
            }
        }
    }
}

__device__ __forceinline__ void load_gU_tiles(float s_g[2][10][19], float s_U[2][9][64],
                                              int b, int th0, int tw0, int tid) {
    {
        float4* dst = (float4*)s_U;
        const float4* src = (const float4*)(g_U + b * 1152);
        for (int i = tid; i < 288; i += 256) dst[i] = src[i];
    }
    if (tid < 180) {
        int r = tid / 18, c2 = tid % 18;
        int gh = th0 + r - 1, gw = tw0 + c2 - 1;
        float v0 = 0.f, v1 = 0.f;
        if (gh >= 0 && gh < HH && gw >= 0 && gw < WW) {
            v0 = g_g[(b * NCLS + 0) * HWSZ + gh * WW + gw];
            v1 = g_g[(b * NCLS + 1) * HWSZ + gh * WW + gw];
        }
        s_g[0][r][c2] = v0;
        s_g[1][r][c2] = v1;
    }
}

// ---------------- kernel 4: BN statistics pass ----------------
__global__ __launch_bounds__(256) void k_bnstats() {
    __shared__ float s_g[2][10][19];
    __shared__ float s_U[2][9][64];
    int b = blockIdx.z;
    int th0 = blockIdx.y * 8, tw0 = blockIdx.x * 16;
    int tid = threadIdx.x;
    load_gU_tiles(s_g, s_U, b, th0, tw0, tid);
    __syncthreads();

    float acc[4][8];
    conv_tile(s_g, s_U, tid, acc);

    int og = tid >> 4;
    int o0 = og * 4;
#pragma unroll
    for (int oo = 0; oo < 4; oo++) {
        int o = o0 + oo;
        float ss = 0.f, s2 = 0.f;
#pragma unroll
        for (int jj = 0; jj < 8; jj++) {
            ss += acc[oo][jj];
            s2 += acc[oo][jj] * acc[oo][jj];
        }
#pragma unroll
        for (int off = 8; off; off >>= 1) {
            ss += __shfl_down_sync(0xffffffffu, ss, off, 16);
            s2 += __shfl_down_sync(0xffffffffu, s2, off, 16);
        }
        if ((tid & 15) == 0) {
            atomicAdd(&g_bnsum[o], ss);
            atomicAdd(&g_bnsq[o], s2);
        }
    }
}

// ---------------- kernel 5: BN finalize ----------------
__global__ void k_bnfin(const float* __restrict__ gamma, const float* __restrict__ beta) {
    int o = threadIdx.x;
    const float nInv = 1.0f / (float)(BB * HWSZ);
    float mean = g_bnsum[o] * nInv;
    float var = g_bnsq[o] * nInv - mean * mean;
    float a = gamma[o] * rsqrtf(var + 1e-5f);
    g_bna[o] = a;
    g_bnb[o] = beta[o] - mean * a;
}

// ---------------- kernel 6: recompute conv, fuse BN+ReLU+residual ----------------
__global__ __launch_bounds__(256) void k_final(const float* __restrict__ x,
                                               float* __restrict__ out) {
    __shared__ float s_g[2][10][19];
    __shared__ float s_U[2][9][64];
    __shared__ float s_a[64], s_b[64];
    int b = blockIdx.z;
    int th0 = blockIdx.y * 8, tw0 = blockIdx.x * 16;
    int tid = threadIdx.x;
    load_gU_tiles(s_g, s_U, b, th0, tw0, tid);
    if (tid >= 192 && tid < 256) {
        int o = tid - 192;
        s_a[o] = g_bna[o];
        s_b[o] = g_bnb[o];
    }
    __syncthreads();

    float acc[4][8];
    conv_tile(s_g, s_U, tid, acc);

    int og = tid >> 4, pg = tid & 15;
    int row = pg >> 1, colb = (pg & 1) * 8;
    int o0 = og * 4;
#pragma unroll
    for (int oo = 0; oo < 4; oo++) {
        int o = o0 + oo;
        float a = s_a[o], bb = s_b[o];
        size_t off = (((size_t)b * CH + o) * HH + th0 + row) * WW + tw0 + colb;
        const float4 xlo = *(const float4*)(x + off);
        const float4 xhi = *(const float4*)(x + off + 4);
        float4 rlo, rhi;
        rlo.x = xlo.x + fmaxf(acc[oo][0] * a + bb, 0.f);
        rlo.y = xlo.y + fmaxf(acc[oo][1] * a + bb, 0.f);
        rlo.z = xlo.z + fmaxf(acc[oo][2] * a + bb, 0.f);
        rlo.w = xlo.w + fmaxf(acc[oo][3] * a + bb, 0.f);
        rhi.x = xhi.x + fmaxf(acc[oo][4] * a + bb, 0.f);
        rhi.y = xhi.y + fmaxf(acc[oo][5] * a + bb, 0.f);
        rhi.z = xhi.z + fmaxf(acc[oo][6] * a + bb, 0.f);
        rhi.w = xhi.w + fmaxf(acc[oo][7] * a + bb, 0.f);
        *(float4*)(out + off) = rlo;
        *(float4*)(out + off + 4) = rhi;
    }
}

// ---------------- launch ----------------
extern "C" void kernel_launch(void* const* d_in, const int* in_sizes, int n_in,
                              void* d_out, int out_size) {
    const float* x      = (const float*)d_in[0];
    const float* cs     = (const float*)d_in[1];
    const float* Wcsp   = (const float*)d_in[2];
    const float* Wx     = (const float*)d_in[3];
    const float* Wcs    = (const float*)d_in[4];
    const float* Wcv    = (const float*)d_in[5];
    const float* Wa     = (const float*)d_in[6];
    const float* Wcomb  = (const float*)d_in[7];
    const float* Wsing  = (const float*)d_in[8];
    const float* gamma  = (const float*)d_in[9];
    const float* beta   = (const float*)d_in[10];
    float* out = (float*)d_out;

    k_init<<<288, 256>>>(Wsing);
    k_spaceg<<<dim3(144, 8), 256>>>(cs, Wcsp, Wcv, Wa, Wcomb);
    k_P<<<dim3(16, 8, 8), 128>>>(x);
    k_tokU<<<8, 256>>>(Wx, Wcs);
    k_bnstats<<<dim3(12, 24, 8), 256>>>();
    k_bnfin<<<1, 64>>>(gamma, beta);
    k_final<<<dim3(12, 24, 8), 256>>>(x, out);
}

// round 11
// speedup vs baseline: 1.1549x; 1.1549x over previous
#include <cuda_runtime.h>
#include <math.h>

// Problem constants
constexpr int BB   = 8;
constexpr int NCLS = 2;
constexpr int NSP  = 8;
constexpr int CH   = 64;
constexpr int HH   = 192;
constexpr int WW   = 192;
constexpr int HWSZ = HH * WW;   // 36864
constexpr int RPS  = 12;        // rows per strip in k_P (16 strips)

// k_P smem layout constants (x stored as duplicated f32x2 pairs)
constexpr int XCHUNK = 102;                // 50 used pairs (100 floats) + 2 pad floats
constexpr int XSLOT  = 4 * XCHUNK;         // 408 floats per row-slot
constexpr int XCP    = 3 * XSLOT;          // 1224
constexpr int SPCOLSTRIDE = 18;
constexpr int SPSZ = 3464;

typedef unsigned long long u64t;

// ---------------- device scratch ----------------
__device__ float g_space[BB * NCLS * NSP * HWSZ];   // [b][sc][hw]
__device__ float g_S[BB * NCLS * NSP];
__device__ float g_P[BB * NSP * NCLS * CH * 9];     // [b][s][c][c'][k]
__device__ float g_wT[CH * CH * 9];                 // [d][k][o]
__device__ float g_U[BB * NCLS * 9 * CH];           // [b][c][k][o]
__device__ float g_g[BB * NCLS * HWSZ];             // [b][c][hw]
__device__ float g_bnsum[CH];
__device__ float g_bnsq[CH];
__device__ float g_bna[CH];
__device__ float g_bnb[CH];

__device__ __forceinline__ float sigmoidf_(float x) {
    return 1.0f / (1.0f + __expf(-x));
}

// ---- packed f32x2 helpers ----
__device__ __forceinline__ u64t pack1(float v) {
    u64t r; asm("mov.b64 %0, {%1, %1};" : "=l"(r) : "f"(v)); return r;
}
__device__ __forceinline__ u64t ffma2(u64t a, u64t b, u64t c) {
    u64t d; asm("fma.rn.f32x2 %0, %1, %2, %3;" : "=l"(d) : "l"(a), "l"(b), "l"(c)); return d;
}
__device__ __forceinline__ float2 unpack2(u64t v) {
    float2 f; asm("mov.b64 {%0, %1}, %2;" : "=f"(f.x), "=f"(f.y) : "l"(v)); return f;
}

// ---------------- kernel: zero accumulators + transpose W_single ----------------
__global__ void k_init(const float* __restrict__ Ws) {
    int i = blockIdx.x * blockDim.x + threadIdx.x;
    if (i < BB * NSP * NCLS * CH * 9) g_P[i] = 0.f;
    if (i < CH) { g_bnsum[i] = 0.f; g_bnsq[i] = 0.f; }
    if (i < BB * NCLS * NSP) g_S[i] = 0.f;
    if (i < CH * CH * 9) {
        int o = i / 576;
        int rem = i % 576;
        int d = rem / 9;
        int k = rem % 9;
        g_wT[d * 576 + k * 64 + o] = Ws[i];
    }
}

// ---------------- kernel 1: space channels + spatial sums + g maps (merged) ----------------
__global__ __launch_bounds__(256) void k_spaceg(const float* __restrict__ cs,
                                                const float* __restrict__ Wcsp,
                                                const float* __restrict__ Wcv,
                                                const float* __restrict__ Wa,
                                                const float* __restrict__ Wcomb) {
    __shared__ float s_q[8], s_wa[8];
    if (threadIdx.x < 8) {
        s_q[threadIdx.x] = Wcomb[threadIdx.x] * Wcv[threadIdx.x];
        s_wa[threadIdx.x] = Wa[threadIdx.x];
    }
    __syncthreads();

    int b = blockIdx.y;
    int p = blockIdx.x * 256 + threadIdx.x;       // 144*256 == HWSZ
    int h = p / WW, w = p % WW;

    float sums[2 * NSP];
#pragma unroll
    for (int c = 0; c < 2; c++) {
        const float* base = cs + (b * NCLS + c) * HWSZ;
        float n[9];
#pragma unroll
        for (int dy = 0; dy < 3; dy++) {
#pragma unroll
            for (int dx = 0; dx < 3; dx++) {
                int gh = h + dy - 1, gw = w + dx - 1;
                float v = 0.f;
                if (gh >= 0 && gh < HH && gw >= 0 && gw < WW)
                    v = sigmoidf_(base[gh * WW + gw]);
                n[dy * 3 + dx] = v;
            }
        }
        float ch0 = n[4];
        g_space[((b * NCLS + c) * NSP + 0) * HWSZ + p] = ch0;
        sums[c * NSP] = ch0;
#pragma unroll
        for (int j = 0; j < 7; j++) {
            float z = 0.f;
#pragma unroll
            for (int k = 0; k < 9; k++) z += Wcsp[j * 9 + k] * n[k];
            float v = sigmoidf_(z);
            g_space[((b * NCLS + c) * NSP + j + 1) * HWSZ + p] = v;
            sums[c * NSP + j + 1] = v;
        }
        float gg = 0.f;
#pragma unroll
        for (int s = 0; s < 8; s++) gg += s_q[s] * sigmoidf_(s_wa[s] * n[4]);
        g_g[(b * NCLS + c) * HWSZ + p] = gg;
    }

#pragma unroll
    for (int sc = 0; sc < 16; sc++) {
        float v = sums[sc];
#pragma unroll
        for (int off = 16; off; off >>= 1)
            v += __shfl_down_sync(0xffffffffu, v, off);
        if ((threadIdx.x & 31) == 0) {
            int c = sc / NSP, s = sc % NSP;
            atomicAdd(&g_S[(b * NCLS + c) * NSP + s], v);
        }
    }
}

// ---------------- kernel 2: P correlation (dup-x f32x2, conflict-free) ----------------
__device__ __forceinline__ void load_x_dup(float* s_x, const float* __restrict__ xb,
                                           int grow, int tid) {
    int slot = ((grow % 3) + 3) % 3;
    bool rok = (grow >= 0 && grow < HH);
    const float* rowp = xb + grow * WW;
#pragma unroll
    for (int m = 0; m < 13; m++) {
        int i = tid + m * 128;
        if (i < 1600) {
            int cp = i / 200;
            int rem = i - cp * 200;
            int j = rem / 50;
            int t = rem - j * 50;
            int col = 48 * j - 1 + t;
            float v = 0.f;
            if (rok && col >= 0 && col < WW) v = rowp[cp * HWSZ + col];
            *(u64t*)(s_x + cp * XCP + slot * XSLOT + j * XCHUNK + 2 * t) = pack1(v);
        }
    }
}

__global__ __launch_bounds__(128) void k_P(const float* __restrict__ x) {
    __shared__ __align__(16) float s_x[8 * XCP];      // 39.2 KB
    __shared__ __align__(16) float s_spT[SPSZ];       // 13.9 KB

    int b = blockIdx.z, cgrp = blockIdx.y, strip = blockIdx.x;
    int r0 = strip * RPS;
    int tid = threadIdx.x;
    int scq = tid >> 5;
    int lane = tid & 31;
    int cpl = lane >> 2;
    int j = lane & 3;
    int scb = scq * 4;

    u64t acc[2][9];
#pragma unroll
    for (int i = 0; i < 2; i++)
#pragma unroll
        for (int k = 0; k < 9; k++) acc[i][k] = 0ull;

    const float* xb = x + (size_t)(b * CH + cgrp * 8) * HWSZ;
    const float* spb = g_space + (size_t)b * 16 * HWSZ;

    load_x_dup(s_x, xb, r0 - 1, tid);
    load_x_dup(s_x, xb, r0, tid);

    const int xoff = cpl * XCP + j * XCHUNK;
    const int spoff = 866 * j + scb;

    int sc_c = tid >> 3;
    int t8 = tid & 7;
    const float* sp_src0 = spb + sc_c * HWSZ + t8;
    float* sp_dst = s_spT + t8 * 18 + sc_c;

    for (int r = r0; r < r0 + RPS; r++) {
        __syncthreads();
        load_x_dup(s_x, xb, r + 1, tid);
        {
            const float* srow = sp_src0 + r * WW;
#pragma unroll
            for (int m = 0; m < 24; m++) {
                sp_dst[144 * m + 2 * (m / 6)] = srow[8 * m];
            }
        }
        __syncthreads();

        int sm1 = (r + 2) % 3;
        int sm0 = r % 3;
        int sp1 = (r + 1) % 3;
        const float* xr0 = s_x + xoff + sm1 * XSLOT;
        const float* xr1 = s_x + xoff + sm0 * XSLOT;
        const float* xr2 = s_x + xoff + sp1 * XSLOT;

        u64t m0 = *(const u64t*)(xr0);
        u64t m1 = *(const u64t*)(xr1);
        u64t m2 = *(const u64t*)(xr2);
        u64t c0 = *(const u64t*)(xr0 + 2);
        u64t c1 = *(const u64t*)(xr1 + 2);
        u64t c2 = *(const u64t*)(xr2 + 2);
        const float* snp = s_spT + spoff;

#pragma unroll 4
        for (int cc = 0; cc < 48; cc++) {
            u64t p0 = *(const u64t*)(xr0 + 2 * (cc + 2));
            u64t p1 = *(const u64t*)(xr1 + 2 * (cc + 2));
            u64t p2 = *(const u64t*)(xr2 + 2 * (cc + 2));
            u64t snA = *(const u64t*)(snp);
            u64t snB = *(const u64t*)(snp + 2);

            acc[0][0] = ffma2(snA, m0, acc[0][0]);
            acc[0][1] = ffma2(snA, c0, acc[0][1]);
            acc[0][2] = ffma2(snA, p0, acc[0][2]);
            acc[0][3] = ffma2(snA, m1, acc[0][3]);
            acc[0][4] = ffma2(snA, c1, acc[0][4]);
            acc[0][5] = ffma2(snA, p1, acc[0][5]);
            acc[0][6] = ffma2(snA, m2, acc[0][6]);
            acc[0][7] = ffma2(snA, c2, acc[0][7]);
            acc[0][8] = ffma2(snA, p2, acc[0][8]);

            acc[1][0] = ffma2(snB, m0, acc[1][0]);
            acc[1][1] = ffma2(snB, c0, acc[1][1]);
            acc[1][2] = ffma2(snB, p0, acc[1][2]);
            acc[1][3] = ffma2(snB, m1, acc[1][3]);
            acc[1][4] = ffma2(snB, c1, acc[1][4]);
            acc[1][5] = ffma2(snB, p1, acc[1][5]);
            acc[1][6] = ffma2(snB, m2, acc[1][6]);
            acc[1][7] = ffma2(snB, c2, acc[1][7]);
            acc[1][8] = ffma2(snB, p2, acc[1][8]);

            m0 = c0; c0 = p0;
            m1 = c1; c1 = p1;
            m2 = c2; c2 = p2;
            snp += SPCOLSTRIDE;
        }
    }

    int cp = cgrp * 8 + cpl;
#pragma unroll
    for (int scp = 0; scp < 2; scp++) {
        int sc0 = scb + scp * 2;
        int sc1 = sc0 + 1;
        int sA = sc0 & 7, cA = sc0 >> 3;
        int sB = sc1 & 7, cB = sc1 >> 3;
        float* dA = &g_P[(((b * 8 + sA) * 2 + cA) * 64 + cp) * 9];
        float* dB = &g_P[(((b * 8 + sB) * 2 + cB) * 64 + cp) * 9];
#pragma unroll
        for (int k = 0; k < 9; k++) {
            float2 v = unpack2(acc[scp][k]);
            atomicAdd(&dA[k], v.x);
            atomicAdd(&dB[k], v.y);
        }
    }
}

// ---------------- kernel 3: tok2 + U, parallel version ----------------
// grid (NCLS, BB) = 16 blocks, block 512.
// Phase 1: thread (s = tid>>6, d = tid&63) computes scaled dot -> smem reduce over s.
// Phase 2: strided loop covers all 576 U outputs.
__global__ __launch_bounds__(512) void k_tokU(const float* __restrict__ Wx,
                                              const float* __restrict__ Wcs) {
    __shared__ float s_part[8][64];
    __shared__ float s_tok[64];
    int c = blockIdx.x, b = blockIdx.y;
    int tid = threadIdx.x;
    int s = tid >> 6;            // 0..7
    int d = tid & 63;

    {
        float inv = Wcs[s] / g_S[(b * NCLS + c) * NSP + s];
        const float4* row = (const float4*)(Wx + (s * CH + d) * 576);
        const float4* pp = (const float4*)(g_P + (((b * NSP + s) * NCLS + c) * CH) * 9);
        float dot = 0.f;
#pragma unroll 8
        for (int m = 0; m < 144; m++) {
            float4 wv = row[m];
            float4 pv = pp[m];
            dot += wv.x * pv.x + wv.y * pv.y + wv.z * pv.z + wv.w * pv.w;
        }
        s_part[s][d] = inv * dot;
    }
    __syncthreads();
    if (tid < 64) {
        float t = 0.f;
#pragma unroll
        for (int si = 0; si < 8; si++) t += s_part[si][tid];
        s_tok[tid] = t;
    }
    __syncthreads();

    // U[b][c][k][o] = sum_d wT[d][k][o] * tok[d]  (576 outputs, strided)
    for (int idx = tid; idx < 576; idx += 512) {
        int k = idx >> 6;        // 0..8
        int o = idx & 63;
        float a = 0.f;
#pragma unroll 8
        for (int dd = 0; dd < 64; dd++)
            a += g_wT[dd * 576 + k * 64 + o] * s_tok[dd];
        g_U[((b * 2 + c) * 9 + k) * 64 + o] = a;
    }
}

// ---------------- shared tile-conv helper ----------------
__device__ __forceinline__ void conv_tile(const float s_g[2][10][19],
                                          const float s_U[2][9][64],
                                          int tid, float acc[4][8]) {
    int og = tid >> 4, pg = tid & 15;
    int row = pg >> 1, colb = (pg & 1) * 8;
    int o0 = og * 4;
#pragma unroll
    for (int oo = 0; oo < 4; oo++)
#pragma unroll
        for (int jj = 0; jj < 8; jj++) acc[oo][jj] = 0.f;
#pragma unroll
    for (int c = 0; c < 2; c++) {
#pragma unroll
        for (int ky = 0; ky < 3; ky++) {
            const float* vrow = &s_g[c][row + ky][colb];
            float v[10];
#pragma unroll
            for (int i = 0; i < 10; i++) v[i] = vrow[i];
#pragma unroll
            for (int kx = 0; kx < 3; kx++) {
                float4 wv = *(const float4*)&s_U[c][ky * 3 + kx][o0];
#pragma unroll
                for (int jj = 0; jj < 8; jj++) {
                    float vv = v[jj + kx];
                    acc[0][jj] += wv.x * vv;
                    acc[1][jj] += wv.y * vv;
                    acc[2][jj] += wv.z * vv;
                    acc[3][jj] += wv.w * vv;
                }
            }
        }
    }
}

__device__ __forceinline__ void load_gU_tiles(float s_g[2][10][19], float s_U[2][9][64],
                                              int b, int th0, int tw0, int tid) {
    {
        float4* dst = (float4*)s_U;
        const float4* src = (const float4*)(g_U + b * 1152);
        for (int i = tid; i < 288; i += 256) dst[i] = src[i];
    }
    if (tid < 180) {
        int r = tid / 18, c2 = tid % 18;
        int gh = th0 + r - 1, gw = tw0 + c2 - 1;
        float v0 = 0.f, v1 = 0.f;
        if (gh >= 0 && gh < HH && gw >= 0 && gw < WW) {
            v0 = g_g[(b * NCLS + 0) * HWSZ + gh * WW + gw];
            v1 = g_g[(b * NCLS + 1) * HWSZ + gh * WW + gw];
        }
        s_g[0][r][c2] = v0;
        s_g[1][r][c2] = v1;
    }
}

// ---------------- kernel 4: BN statistics pass ----------------
__global__ __launch_bounds__(256) void k_bnstats() {
    __shared__ float s_g[2][10][19];
    __shared__ float s_U[2][9][64];
    int b = blockIdx.z;
    int th0 = blockIdx.y * 8, tw0 = blockIdx.x * 16;
    int tid = threadIdx.x;
    load_gU_tiles(s_g, s_U, b, th0, tw0, tid);
    __syncthreads();

    float acc[4][8];
    conv_tile(s_g, s_U, tid, acc);

    int og = tid >> 4;
    int o0 = og * 4;
#pragma unroll
    for (int oo = 0; oo < 4; oo++) {
        int o = o0 + oo;
        float ss = 0.f, s2 = 0.f;
#pragma unroll
        for (int jj = 0; jj < 8; jj++) {
            ss += acc[oo][jj];
            s2 += acc[oo][jj] * acc[oo][jj];
        }
#pragma unroll
        for (int off = 8; off; off >>= 1) {
            ss += __shfl_down_sync(0xffffffffu, ss, off, 16);
            s2 += __shfl_down_sync(0xffffffffu, s2, off, 16);
        }
        if ((tid & 15) == 0) {
            atomicAdd(&g_bnsum[o], ss);
            atomicAdd(&g_bnsq[o], s2);
        }
    }
}

// ---------------- kernel 5: BN finalize ----------------
__global__ void k_bnfin(const float* __restrict__ gamma, const float* __restrict__ beta) {
    int o = threadIdx.x;
    const float nInv = 1.0f / (float)(BB * HWSZ);
    float mean = g_bnsum[o] * nInv;
    float var = g_bnsq[o] * nInv - mean * mean;
    float a = gamma[o] * rsqrtf(var + 1e-5f);
    g_bna[o] = a;
    g_bnb[o] = beta[o] - mean * a;
}

// ---------------- kernel 6: recompute conv, fuse BN+ReLU+residual ----------------
__global__ __launch_bounds__(256) void k_final(const float* __restrict__ x,
                                               float* __restrict__ out) {
    __shared__ float s_g[2][10][19];
    __shared__ float s_U[2][9][64];
    __shared__ float s_a[64], s_b[64];
    int b = blockIdx.z;
    int th0 = blockIdx.y * 8, tw0 = blockIdx.x * 16;
    int tid = threadIdx.x;
    load_gU_tiles(s_g, s_U, b, th0, tw0, tid);
    if (tid >= 192 && tid < 256) {
        int o = tid - 192;
        s_a[o] = g_bna[o];
        s_b[o] = g_bnb[o];
    }
    __syncthreads();

    float acc[4][8];
    conv_tile(s_g, s_U, tid, acc);

    int og = tid >> 4, pg = tid & 15;
    int row = pg >> 1, colb = (pg & 1) * 8;
    int o0 = og * 4;
#pragma unroll
    for (int oo = 0; oo < 4; oo++) {
        int o = o0 + oo;
        float a = s_a[o], bb = s_b[o];
        size_t off = (((size_t)b * CH + o) * HH + th0 + row) * WW + tw0 + colb;
        const float4 xlo = *(const float4*)(x + off);
        const float4 xhi = *(const float4*)(x + off + 4);
        float4 rlo, rhi;
        rlo.x = xlo.x + fmaxf(acc[oo][0] * a + bb, 0.f);
        rlo.y = xlo.y + fmaxf(acc[oo][1] * a + bb, 0.f);
        rlo.z = xlo.z + fmaxf(acc[oo][2] * a + bb, 0.f);
        rlo.w = xlo.w + fmaxf(acc[oo][3] * a + bb, 0.f);
        rhi.x = xhi.x + fmaxf(acc[oo][4] * a + bb, 0.f);
        rhi.y = xhi.y + fmaxf(acc[oo][5] * a + bb, 0.f);
        rhi.z = xhi.z + fmaxf(acc[oo][6] * a + bb, 0.f);
        rhi.w = xhi.w + fmaxf(acc[oo][7] * a + bb, 0.f);
        *(float4*)(out + off) = rlo;
        *(float4*)(out + off + 4) = rhi;
    }
}

// ---------------- launch ----------------
extern "C" void kernel_launch(void* const* d_in, const int* in_sizes, int n_in,
                              void* d_out, int out_size) {
    const float* x      = (const float*)d_in[0];
    const float* cs     = (const float*)d_in[1];
    const float* Wcsp   = (const float*)d_in[2];
    const float* Wx     = (const float*)d_in[3];
    const float* Wcs    = (const float*)d_in[4];
    const float* Wcv    = (const float*)d_in[5];
    const float* Wa     = (const float*)d_in[6];
    const float* Wcomb  = (const float*)d_in[7];
    const float* Wsing  = (const float*)d_in[8];
    const float* gamma  = (const float*)d_in[9];
    const float* beta   = (const float*)d_in[10];
    float* out = (float*)d_out;

    k_init<<<288, 256>>>(Wsing);
    k_spaceg<<<dim3(144, 8), 256>>>(cs, Wcsp, Wcv, Wa, Wcomb);
    k_P<<<dim3(16, 8, 8), 128>>>(x);
    k_tokU<<<dim3(NCLS, BB), 512>>>(Wx, Wcs);
    k_bnstats<<<dim3(12, 24, 8), 256>>>();
    k_bnfin<<<1, 64>>>(gamma, beta);
    k_final<<<dim3(12, 24, 8), 256>>>(x, out);
}

// round 12
// speedup vs baseline: 1.5206x; 1.3167x over previous
#include <cuda_runtime.h>
#include <math.h>

// Problem constants
constexpr int BB   = 8;
constexpr int NCLS = 2;
constexpr int NSP  = 8;
constexpr int CH   = 64;
constexpr int HH   = 192;
constexpr int WW   = 192;
constexpr int HWSZ = HH * WW;   // 36864
constexpr int RPS  = 12;        // rows per strip in k_P (16 strips)

// k_P smem layout constants (x stored as duplicated f32x2 pairs)
constexpr int XCHUNK = 102;
constexpr int XSLOT  = 4 * XCHUNK;         // 408
constexpr int XCP    = 3 * XSLOT;          // 1224
constexpr int SPCOLSTRIDE = 18;
constexpr int SPSZ = 3464;

typedef unsigned long long u64t;

// ---------------- device scratch ----------------
__device__ float g_space[BB * NCLS * NSP * HWSZ];   // [b][sc][hw]
__device__ float g_S[BB * NCLS * NSP];
__device__ float g_P[BB * NSP * NCLS * CH * 9];     // [b][s][c][c'][k]
__device__ float g_tok[BB * NCLS * CH];             // [b][c][d]
__device__ float g_wT[CH * CH * 9];                 // [d][k][o]
__device__ float g_U[BB * NCLS * 9 * CH];           // [b][c][k][o]
__device__ float g_g[BB * NCLS * HWSZ];             // [b][c][hw]
__device__ float g_bnsum[CH];
__device__ float g_bnsq[CH];

__device__ __forceinline__ float sigmoidf_(float x) {
    return 1.0f / (1.0f + __expf(-x));
}

// ---- packed f32x2 helpers ----
__device__ __forceinline__ u64t pack1(float v) {
    u64t r; asm("mov.b64 %0, {%1, %1};" : "=l"(r) : "f"(v)); return r;
}
__device__ __forceinline__ u64t ffma2(u64t a, u64t b, u64t c) {
    u64t d; asm("fma.rn.f32x2 %0, %1, %2, %3;" : "=l"(d) : "l"(a), "l"(b), "l"(c)); return d;
}
__device__ __forceinline__ float2 unpack2(u64t v) {
    float2 f; asm("mov.b64 {%0, %1}, %2;" : "=f"(f.x), "=f"(f.y) : "l"(v)); return f;
}

// ---------------- kernel: zero accumulators + transpose W_single ----------------
__global__ void k_init(const float* __restrict__ Ws) {
    int i = blockIdx.x * blockDim.x + threadIdx.x;
    if (i < BB * NSP * NCLS * CH * 9) g_P[i] = 0.f;
    if (i < CH) { g_bnsum[i] = 0.f; g_bnsq[i] = 0.f; }
    if (i < BB * NCLS * NSP) g_S[i] = 0.f;
    if (i < BB * NCLS * CH) g_tok[i] = 0.f;
    if (i < CH * CH * 9) {
        int o = i / 576;
        int rem = i % 576;
        int d = rem / 9;
        int k = rem % 9;
        g_wT[d * 576 + k * 64 + o] = Ws[i];
    }
}

// ---------------- kernel 1: space channels + sums + g maps (smem-staged sigmoid) ----------------
// grid (24, 8): 8-row tiles. block 256, 6 pixels/thread.
__global__ __launch_bounds__(256) void k_spaceg(const float* __restrict__ cs,
                                                const float* __restrict__ Wcsp,
                                                const float* __restrict__ Wcv,
                                                const float* __restrict__ Wa,
                                                const float* __restrict__ Wcomb) {
    __shared__ float s_sig[2][10][194];   // sigmoid(cs) tile with halo
    __shared__ float s_q[8], s_wa[8];
    int tid = threadIdx.x;
    int b = blockIdx.y;
    int r0 = blockIdx.x * 8;

    if (tid < 8) {
        s_q[tid] = Wcomb[tid] * Wcv[tid];
        s_wa[tid] = Wa[tid];
    }

    // load sigmoid tile: 2 classes x 10 rows x 194 cols
    for (int i = tid; i < 2 * 10 * 194; i += 256) {
        int c = i / 1940;
        int rem = i - c * 1940;
        int rr = rem / 194;
        int cc = rem - rr * 194;
        int gh = r0 + rr - 1, gw = cc - 1;
        float v = 0.f;
        if (gh >= 0 && gh < HH && gw >= 0 && gw < WW)
            v = sigmoidf_(cs[(b * NCLS + c) * HWSZ + gh * WW + gw]);
        s_sig[c][rr][cc] = v;
    }
    __syncthreads();

    float sums[2 * NSP];
#pragma unroll
    for (int i = 0; i < 16; i++) sums[i] = 0.f;

#pragma unroll
    for (int pi = 0; pi < 6; pi++) {
        int pl = tid + pi * 256;           // 0..1535
        int lr = pl / WW, w = pl - lr * WW;
        int p = (r0 + lr) * WW + w;
#pragma unroll
        for (int c = 0; c < 2; c++) {
            float n[9];
#pragma unroll
            for (int dy = 0; dy < 3; dy++)
#pragma unroll
                for (int dx = 0; dx < 3; dx++)
                    n[dy * 3 + dx] = s_sig[c][lr + dy][w + dx];

            float ch0 = n[4];
            g_space[((b * NCLS + c) * NSP + 0) * HWSZ + p] = ch0;
            sums[c * NSP] += ch0;
#pragma unroll
            for (int j = 0; j < 7; j++) {
                float z = 0.f;
#pragma unroll
                for (int k = 0; k < 9; k++) z += Wcsp[j * 9 + k] * n[k];
                float v = sigmoidf_(z);
                g_space[((b * NCLS + c) * NSP + j + 1) * HWSZ + p] = v;
                sums[c * NSP + j + 1] += v;
            }
            float gg = 0.f;
#pragma unroll
            for (int s = 0; s < 8; s++) gg += s_q[s] * sigmoidf_(s_wa[s] * ch0);
            g_g[(b * NCLS + c) * HWSZ + p] = gg;
        }
    }

#pragma unroll
    for (int sc = 0; sc < 16; sc++) {
        float v = sums[sc];
#pragma unroll
        for (int off = 16; off; off >>= 1)
            v += __shfl_down_sync(0xffffffffu, v, off);
        if ((tid & 31) == 0) {
            int c = sc / NSP, s = sc % NSP;
            atomicAdd(&g_S[(b * NCLS + c) * NSP + s], v);
        }
    }
}

// ---------------- kernel 2: P correlation (dup-x f32x2, conflict-free) ----------------
__device__ __forceinline__ void load_x_dup(float* s_x, const float* __restrict__ xb,
                                           int grow, int tid) {
    int slot = ((grow % 3) + 3) % 3;
    bool rok = (grow >= 0 && grow < HH);
    const float* rowp = xb + grow * WW;
#pragma unroll
    for (int m = 0; m < 13; m++) {
        int i = tid + m * 128;
        if (i < 1600) {
            int cp = i / 200;
            int rem = i - cp * 200;
            int j = rem / 50;
            int t = rem - j * 50;
            int col = 48 * j - 1 + t;
            float v = 0.f;
            if (rok && col >= 0 && col < WW) v = rowp[cp * HWSZ + col];
            *(u64t*)(s_x + cp * XCP + slot * XSLOT + j * XCHUNK + 2 * t) = pack1(v);
        }
    }
}

__global__ __launch_bounds__(128) void k_P(const float* __restrict__ x) {
    __shared__ __align__(16) float s_x[8 * XCP];      // 39.2 KB
    __shared__ __align__(16) float s_spT[SPSZ];       // 13.9 KB

    int b = blockIdx.z, cgrp = blockIdx.y, strip = blockIdx.x;
    int r0 = strip * RPS;
    int tid = threadIdx.x;
    int scq = tid >> 5;
    int lane = tid & 31;
    int cpl = lane >> 2;
    int j = lane & 3;
    int scb = scq * 4;

    u64t acc[2][9];
#pragma unroll
    for (int i = 0; i < 2; i++)
#pragma unroll
        for (int k = 0; k < 9; k++) acc[i][k] = 0ull;

    const float* xb = x + (size_t)(b * CH + cgrp * 8) * HWSZ;
    const float* spb = g_space + (size_t)b * 16 * HWSZ;

    load_x_dup(s_x, xb, r0 - 1, tid);
    load_x_dup(s_x, xb, r0, tid);

    const int xoff = cpl * XCP + j * XCHUNK;
    const int spoff = 866 * j + scb;

    int sc_c = tid >> 3;
    int t8 = tid & 7;
    const float* sp_src0 = spb + sc_c * HWSZ + t8;
    float* sp_dst = s_spT + t8 * 18 + sc_c;

    for (int r = r0; r < r0 + RPS; r++) {
        __syncthreads();
        load_x_dup(s_x, xb, r + 1, tid);
        {
            const float* srow = sp_src0 + r * WW;
#pragma unroll
            for (int m = 0; m < 24; m++) {
                sp_dst[144 * m + 2 * (m / 6)] = srow[8 * m];
            }
        }
        __syncthreads();

        int sm1 = (r + 2) % 3;
        int sm0 = r % 3;
        int sp1 = (r + 1) % 3;
        const float* xr0 = s_x + xoff + sm1 * XSLOT;
        const float* xr1 = s_x + xoff + sm0 * XSLOT;
        const float* xr2 = s_x + xoff + sp1 * XSLOT;

        u64t m0 = *(const u64t*)(xr0);
        u64t m1 = *(const u64t*)(xr1);
        u64t m2 = *(const u64t*)(xr2);
        u64t c0 = *(const u64t*)(xr0 + 2);
        u64t c1 = *(const u64t*)(xr1 + 2);
        u64t c2 = *(const u64t*)(xr2 + 2);
        const float* snp = s_spT + spoff;

#pragma unroll 4
        for (int cc = 0; cc < 48; cc++) {
            u64t p0 = *(const u64t*)(xr0 + 2 * (cc + 2));
            u64t p1 = *(const u64t*)(xr1 + 2 * (cc + 2));
            u64t p2 = *(const u64t*)(xr2 + 2 * (cc + 2));
            u64t snA = *(const u64t*)(snp);
            u64t snB = *(const u64t*)(snp + 2);

            acc[0][0] = ffma2(snA, m0, acc[0][0]);
            acc[0][1] = ffma2(snA, c0, acc[0][1]);
            acc[0][2] = ffma2(snA, p0, acc[0][2]);
            acc[0][3] = ffma2(snA, m1, acc[0][3]);
            acc[0][4] = ffma2(snA, c1, acc[0][4]);
            acc[0][5] = ffma2(snA, p1, acc[0][5]);
            acc[0][6] = ffma2(snA, m2, acc[0][6]);
            acc[0][7] = ffma2(snA, c2, acc[0][7]);
            acc[0][8] = ffma2(snA, p2, acc[0][8]);

            acc[1][0] = ffma2(snB, m0, acc[1][0]);
            acc[1][1] = ffma2(snB, c0, acc[1][1]);
            acc[1][2] = ffma2(snB, p0, acc[1][2]);
            acc[1][3] = ffma2(snB, m1, acc[1][3]);
            acc[1][4] = ffma2(snB, c1, acc[1][4]);
            acc[1][5] = ffma2(snB, p1, acc[1][5]);
            acc[1][6] = ffma2(snB, m2, acc[1][6]);
            acc[1][7] = ffma2(snB, c2, acc[1][7]);
            acc[1][8] = ffma2(snB, p2, acc[1][8]);

            m0 = c0; c0 = p0;
            m1 = c1; c1 = p1;
            m2 = c2; c2 = p2;
            snp += SPCOLSTRIDE;
        }
    }

    int cp = cgrp * 8 + cpl;
#pragma unroll
    for (int scp = 0; scp < 2; scp++) {
        int sc0 = scb + scp * 2;
        int sc1 = sc0 + 1;
        int sA = sc0 & 7, cA = sc0 >> 3;
        int sB = sc1 & 7, cB = sc1 >> 3;
        float* dA = &g_P[(((b * 8 + sA) * 2 + cA) * 64 + cp) * 9];
        float* dB = &g_P[(((b * 8 + sB) * 2 + cB) * 64 + cp) * 9];
#pragma unroll
        for (int k = 0; k < 9; k++) {
            float2 v = unpack2(acc[scp][k]);
            atomicAdd(&dA[k], v.x);
            atomicAdd(&dB[k], v.y);
        }
    }
}

// ---------------- kernel 3a: tok[b][c][d] (parallel, deep MLP) ----------------
// grid (8s, 2c, 8b) = 128 blocks, block 256: thread = (quarter q, d).
__global__ __launch_bounds__(256) void k_tok(const float* __restrict__ Wx,
                                             const float* __restrict__ Wcs) {
    __shared__ float s_part[4][64];
    int s = blockIdx.x, c = blockIdx.y, b = blockIdx.z;
    int tid = threadIdx.x;
    int d = tid & 63;
    int q = tid >> 6;            // 0..3

    const float4* row = (const float4*)(Wx + (s * CH + d) * 576) + q * 36;
    const float4* pp = (const float4*)(g_P + (((b * NSP + s) * NCLS + c) * CH) * 9) + q * 36;
    float dot = 0.f;
#pragma unroll
    for (int m = 0; m < 36; m++) {
        float4 wv = row[m];
        float4 pv = pp[m];
        dot += wv.x * pv.x + wv.y * pv.y + wv.z * pv.z + wv.w * pv.w;
    }
    s_part[q][d] = dot;
    __syncthreads();
    if (tid < 64) {
        float inv = Wcs[s] / g_S[(b * NCLS + c) * NSP + s];
        float t = s_part[0][tid] + s_part[1][tid] + s_part[2][tid] + s_part[3][tid];
        atomicAdd(&g_tok[(b * NCLS + c) * CH + tid], inv * t);
    }
}

// ---------------- kernel 3b: U[b][c][k][o] ----------------
// grid (2c, 8b) = 16 blocks, block 576: thread = (k, o).
__global__ __launch_bounds__(576) void k_U() {
    __shared__ float s_tok[64];
    int c = blockIdx.x, b = blockIdx.y;
    int tid = threadIdx.x;
    if (tid < 64) s_tok[tid] = g_tok[(b * NCLS + c) * CH + tid];
    __syncthreads();
    int k = tid >> 6;            // 0..8
    int o = tid & 63;
    float a = 0.f;
#pragma unroll 16
    for (int dd = 0; dd < 64; dd++)
        a += g_wT[dd * 576 + k * 64 + o] * s_tok[dd];
    g_U[((b * 2 + c) * 9 + k) * 64 + o] = a;
}

// ---------------- shared tile-conv helper ----------------
__device__ __forceinline__ void conv_tile(const float s_g[2][10][19],
                                          const float s_U[2][9][64],
                                          int tid, float acc[4][8]) {
    int og = tid >> 4, pg = tid & 15;
    int row = pg >> 1, colb = (pg & 1) * 8;
    int o0 = og * 4;
#pragma unroll
    for (int oo = 0; oo < 4; oo++)
#pragma unroll
        for (int jj = 0; jj < 8; jj++) acc[oo][jj] = 0.f;
#pragma unroll
    for (int c = 0; c < 2; c++) {
#pragma unroll
        for (int ky = 0; ky < 3; ky++) {
            const float* vrow = &s_g[c][row + ky][colb];
            float v[10];
#pragma unroll
            for (int i = 0; i < 10; i++) v[i] = vrow[i];
#pragma unroll
            for (int kx = 0; kx < 3; kx++) {
                float4 wv = *(const float4*)&s_U[c][ky * 3 + kx][o0];
#pragma unroll
                for (int jj = 0; jj < 8; jj++) {
                    float vv = v[jj + kx];
                    acc[0][jj] += wv.x * vv;
                    acc[1][jj] += wv.y * vv;
                    acc[2][jj] += wv.z * vv;
                    acc[3][jj] += wv.w * vv;
                }
            }
        }
    }
}

__device__ __forceinline__ void load_gU_tiles(float s_g[2][10][19], float s_U[2][9][64],
                                              int b, int th0, int tw0, int tid) {
    {
        float4* dst = (float4*)s_U;
        const float4* src = (const float4*)(g_U + b * 1152);
        for (int i = tid; i < 288; i += 256) dst[i] = src[i];
    }
    if (tid < 180) {
        int r = tid / 18, c2 = tid % 18;
        int gh = th0 + r - 1, gw = tw0 + c2 - 1;
        float v0 = 0.f, v1 = 0.f;
        if (gh >= 0 && gh < HH && gw >= 0 && gw < WW) {
            v0 = g_g[(b * NCLS + 0) * HWSZ + gh * WW + gw];
            v1 = g_g[(b * NCLS + 1) * HWSZ + gh * WW + gw];
        }
        s_g[0][r][c2] = v0;
        s_g[1][r][c2] = v1;
    }
}

// ---------------- kernel 4: BN statistics pass ----------------
__global__ __launch_bounds__(256) void k_bnstats() {
    __shared__ float s_g[2][10][19];
    __shared__ float s_U[2][9][64];
    int b = blockIdx.z;
    int th0 = blockIdx.y * 8, tw0 = blockIdx.x * 16;
    int tid = threadIdx.x;
    load_gU_tiles(s_g, s_U, b, th0, tw0, tid);
    __syncthreads();

    float acc[4][8];
    conv_tile(s_g, s_U, tid, acc);

    int og = tid >> 4;
    int o0 = og * 4;
#pragma unroll
    for (int oo = 0; oo < 4; oo++) {
        int o = o0 + oo;
        float ss = 0.f, s2 = 0.f;
#pragma unroll
        for (int jj = 0; jj < 8; jj++) {
            ss += acc[oo][jj];
            s2 += acc[oo][jj] * acc[oo][jj];
        }
#pragma unroll
        for (int off = 8; off; off >>= 1) {
            ss += __shfl_down_sync(0xffffffffu, ss, off, 16);
            s2 += __shfl_down_sync(0xffffffffu, s2, off, 16);
        }
        if ((tid & 15) == 0) {
            atomicAdd(&g_bnsum[o], ss);
            atomicAdd(&g_bnsq[o], s2);
        }
    }
}

// ---------------- kernel 5: recompute conv, fuse BNfin+BN+ReLU+residual ----------------
__global__ __launch_bounds__(256) void k_final(const float* __restrict__ x,
                                               const float* __restrict__ gamma,
                                               const float* __restrict__ beta,
                                               float* __restrict__ out) {
    __shared__ float s_g[2][10][19];
    __shared__ float s_U[2][9][64];
    __shared__ float s_a[64], s_b[64];
    int b = blockIdx.z;
    int th0 = blockIdx.y * 8, tw0 = blockIdx.x * 16;
    int tid = threadIdx.x;
    load_gU_tiles(s_g, s_U, b, th0, tw0, tid);
    if (tid >= 192 && tid < 256) {
        int o = tid - 192;
        const float nInv = 1.0f / (float)(BB * HWSZ);
        float mean = g_bnsum[o] * nInv;
        float var = g_bnsq[o] * nInv - mean * mean;
        float a = gamma[o] * rsqrtf(var + 1e-5f);
        s_a[o] = a;
        s_b[o] = beta[o] - mean * a;
    }
    __syncthreads();

    float acc[4][8];
    conv_tile(s_g, s_U, tid, acc);

    int og = tid >> 4, pg = tid & 15;
    int row = pg >> 1, colb = (pg & 1) * 8;
    int o0 = og * 4;
#pragma unroll
    for (int oo = 0; oo < 4; oo++) {
        int o = o0 + oo;
        float a = s_a[o], bb = s_b[o];
        size_t off = (((size_t)b * CH + o) * HH + th0 + row) * WW + tw0 + colb;
        const float4 xlo = *(const float4*)(x + off);
        const float4 xhi = *(const float4*)(x + off + 4);
        float4 rlo, rhi;
        rlo.x = xlo.x + fmaxf(acc[oo][0] * a + bb, 0.f);
        rlo.y = xlo.y + fmaxf(acc[oo][1] * a + bb, 0.f);
        rlo.z = xlo.z + fmaxf(acc[oo][2] * a + bb, 0.f);
        rlo.w = xlo.w + fmaxf(acc[oo][3] * a + bb, 0.f);
        rhi.x = xhi.x + fmaxf(acc[oo][4] * a + bb, 0.f);
        rhi.y = xhi.y + fmaxf(acc[oo][5] * a + bb, 0.f);
        rhi.z = xhi.z + fmaxf(acc[oo][6] * a + bb, 0.f);
        rhi.w = xhi.w + fmaxf(acc[oo][7] * a + bb, 0.f);
        *(float4*)(out + off) = rlo;
        *(float4*)(out + off + 4) = rhi;
    }
}

// ---------------- launch ----------------
extern "C" void kernel_launch(void* const* d_in, const int* in_sizes, int n_in,
                              void* d_out, int out_size) {
    const float* x      = (const float*)d_in[0];
    const float* cs     = (const float*)d_in[1];
    const float* Wcsp   = (const float*)d_in[2];
    const float* Wx     = (const float*)d_in[3];
    const float* Wcs    = (const float*)d_in[4];
    const float* Wcv    = (const float*)d_in[5];
    const float* Wa     = (const float*)d_in[6];
    const float* Wcomb  = (const float*)d_in[7];
    const float* Wsing  = (const float*)d_in[8];
    const float* gamma  = (const float*)d_in[9];
    const float* beta   = (const float*)d_in[10];
    float* out = (float*)d_out;

    k_init<<<288, 256>>>(Wsing);
    k_spaceg<<<dim3(24, 8), 256>>>(cs, Wcsp, Wcv, Wa, Wcomb);
    k_P<<<dim3(16, 8, 8), 128>>>(x);
    k_tok<<<dim3(8, 2, 8), 256>>>(Wx, Wcs);
    k_U<<<dim3(2, 8), 576>>>();
    k_bnstats<<<dim3(12, 24, 8), 256>>>();
    k_final<<<dim3(12, 24, 8), 256>>>(x, gamma, beta, out);
}

// round 13
// speedup vs baseline: 1.5241x; 1.0024x over previous
#include <cuda_runtime.h>
#include <math.h>

// Problem constants
constexpr int BB   = 8;
constexpr int NCLS = 2;
constexpr int NSP  = 8;
constexpr int CH   = 64;
constexpr int HH   = 192;
constexpr int WW   = 192;
constexpr int HWSZ = HH * WW;   // 36864
constexpr int RPS  = 12;        // rows per strip in k_P (16 strips)

// k_P smem layout constants (x stored as duplicated f32x2 pairs)
constexpr int XCHUNK = 102;
constexpr int XSLOT  = 4 * XCHUNK;         // 408
constexpr int XCP    = 3 * XSLOT;          // 1224
constexpr int SPCOLSTRIDE = 18;
constexpr int SPSZ = 3464;

typedef unsigned long long u64t;

// ---------------- device scratch ----------------
__device__ float g_space[BB * NCLS * NSP * HWSZ];   // [b][sc][hw]
__device__ float g_S[BB * NCLS * NSP];
__device__ float g_P[BB * NSP * NCLS * CH * 9];     // [b][s][c][c'][k]
__device__ float g_tok[BB * NCLS * CH];             // [b][c][d]
__device__ float g_wT[CH * CH * 9];                 // [d][k][o]
__device__ float g_U[BB * NCLS * 9 * CH];           // [b][c][k][o]
__device__ float g_g[BB * NCLS * HWSZ];             // [b][c][hw]
__device__ float g_bnsum[CH];
__device__ float g_bnsq[CH];

__device__ __forceinline__ float sigmoidf_(float x) {
    return 1.0f / (1.0f + __expf(-x));
}

// ---- packed f32x2 helpers ----
__device__ __forceinline__ u64t pack1(float v) {
    u64t r; asm("mov.b64 %0, {%1, %1};" : "=l"(r) : "f"(v)); return r;
}
__device__ __forceinline__ u64t ffma2(u64t a, u64t b, u64t c) {
    u64t d; asm("fma.rn.f32x2 %0, %1, %2, %3;" : "=l"(d) : "l"(a), "l"(b), "l"(c)); return d;
}
__device__ __forceinline__ float2 unpack2(u64t v) {
    float2 f; asm("mov.b64 {%0, %1}, %2;" : "=f"(f.x), "=f"(f.y) : "l"(v)); return f;
}

// ---------------- kernel 0a: zero accumulators ----------------
__global__ void k_zero() {
    int i = blockIdx.x * blockDim.x + threadIdx.x;
    if (i < BB * NSP * NCLS * CH * 9) g_P[i] = 0.f;
    if (i < CH) { g_bnsum[i] = 0.f; g_bnsq[i] = 0.f; }
    if (i < BB * NCLS * NSP) g_S[i] = 0.f;
    if (i < BB * NCLS * CH) g_tok[i] = 0.f;
}

// ---------------- kernel 0b: transpose W_single (OIHW -> [d][k][o]) ----------------
__global__ void k_wT(const float* __restrict__ Ws) {
    int i = blockIdx.x * blockDim.x + threadIdx.x;
    if (i < CH * CH * 9) {
        int o = i / 576;
        int rem = i % 576;
        int d = rem / 9;
        int k = rem % 9;
        g_wT[d * 576 + k * 64 + o] = Ws[i];
    }
}

// ---------------- kernel 1: space channels + sums + g maps (4-row tiles) ----------------
// grid (48, 8): 4-row tiles for wave balance. block 256, 3 pixels/thread.
__global__ __launch_bounds__(256) void k_spaceg(const float* __restrict__ cs,
                                                const float* __restrict__ Wcsp,
                                                const float* __restrict__ Wcv,
                                                const float* __restrict__ Wa,
                                                const float* __restrict__ Wcomb) {
    __shared__ float s_sig[2][6][194];   // sigmoid(cs) tile with halo
    __shared__ float s_q[8], s_wa[8];
    int tid = threadIdx.x;
    int b = blockIdx.y;
    int r0 = blockIdx.x * 4;

    if (tid < 8) {
        s_q[tid] = Wcomb[tid] * Wcv[tid];
        s_wa[tid] = Wa[tid];
    }

    // load sigmoid tile: 2 classes x 6 rows x 194 cols
    for (int i = tid; i < 2 * 6 * 194; i += 256) {
        int c = i / 1164;
        int rem = i - c * 1164;
        int rr = rem / 194;
        int cc = rem - rr * 194;
        int gh = r0 + rr - 1, gw = cc - 1;
        float v = 0.f;
        if (gh >= 0 && gh < HH && gw >= 0 && gw < WW)
            v = sigmoidf_(cs[(b * NCLS + c) * HWSZ + gh * WW + gw]);
        s_sig[c][rr][cc] = v;
    }
    __syncthreads();

    float sums[2 * NSP];
#pragma unroll
    for (int i = 0; i < 16; i++) sums[i] = 0.f;

#pragma unroll
    for (int pi = 0; pi < 3; pi++) {
        int pl = tid + pi * 256;           // 0..767
        int lr = pl / WW, w = pl - lr * WW;
        int p = (r0 + lr) * WW + w;
#pragma unroll
        for (int c = 0; c < 2; c++) {
            float n[9];
#pragma unroll
            for (int dy = 0; dy < 3; dy++)
#pragma unroll
                for (int dx = 0; dx < 3; dx++)
                    n[dy * 3 + dx] = s_sig[c][lr + dy][w + dx];

            float ch0 = n[4];
            g_space[((b * NCLS + c) * NSP + 0) * HWSZ + p] = ch0;
            sums[c * NSP] += ch0;
#pragma unroll
            for (int j = 0; j < 7; j++) {
                float z = 0.f;
#pragma unroll
                for (int k = 0; k < 9; k++) z += Wcsp[j * 9 + k] * n[k];
                float v = sigmoidf_(z);
                g_space[((b * NCLS + c) * NSP + j + 1) * HWSZ + p] = v;
                sums[c * NSP + j + 1] += v;
            }
            float gg = 0.f;
#pragma unroll
            for (int s = 0; s < 8; s++) gg += s_q[s] * sigmoidf_(s_wa[s] * ch0);
            g_g[(b * NCLS + c) * HWSZ + p] = gg;
        }
    }

#pragma unroll
    for (int sc = 0; sc < 16; sc++) {
        float v = sums[sc];
#pragma unroll
        for (int off = 16; off; off >>= 1)
            v += __shfl_down_sync(0xffffffffu, v, off);
        if ((tid & 31) == 0) {
            int c = sc / NSP, s = sc % NSP;
            atomicAdd(&g_S[(b * NCLS + c) * NSP + s], v);
        }
    }
}

// ---------------- kernel 2: P correlation (dup-x f32x2, conflict-free) ----------------
__device__ __forceinline__ void load_x_dup(float* s_x, const float* __restrict__ xb,
                                           int grow, int tid) {
    int slot = ((grow % 3) + 3) % 3;
    bool rok = (grow >= 0 && grow < HH);
    const float* rowp = xb + grow * WW;
#pragma unroll
    for (int m = 0; m < 13; m++) {
        int i = tid + m * 128;
        if (i < 1600) {
            int cp = i / 200;
            int rem = i - cp * 200;
            int j = rem / 50;
            int t = rem - j * 50;
            int col = 48 * j - 1 + t;
            float v = 0.f;
            if (rok && col >= 0 && col < WW) v = rowp[cp * HWSZ + col];
            *(u64t*)(s_x + cp * XCP + slot * XSLOT + j * XCHUNK + 2 * t) = pack1(v);
        }
    }
}

__global__ __launch_bounds__(128) void k_P(const float* __restrict__ x) {
    __shared__ __align__(16) float s_x[8 * XCP];      // 39.2 KB
    __shared__ __align__(16) float s_spT[SPSZ];       // 13.9 KB

    int b = blockIdx.z, cgrp = blockIdx.y, strip = blockIdx.x;
    int r0 = strip * RPS;
    int tid = threadIdx.x;
    int scq = tid >> 5;
    int lane = tid & 31;
    int cpl = lane >> 2;
    int j = lane & 3;
    int scb = scq * 4;

    u64t acc[2][9];
#pragma unroll
    for (int i = 0; i < 2; i++)
#pragma unroll
        for (int k = 0; k < 9; k++) acc[i][k] = 0ull;

    const float* xb = x + (size_t)(b * CH + cgrp * 8) * HWSZ;
    const float* spb = g_space + (size_t)b * 16 * HWSZ;

    load_x_dup(s_x, xb, r0 - 1, tid);
    load_x_dup(s_x, xb, r0, tid);

    const int xoff = cpl * XCP + j * XCHUNK;
    const int spoff = 866 * j + scb;

    int sc_c = tid >> 3;
    int t8 = tid & 7;
    const float* sp_src0 = spb + sc_c * HWSZ + t8;
    float* sp_dst = s_spT + t8 * 18 + sc_c;

    for (int r = r0; r < r0 + RPS; r++) {
        __syncthreads();
        load_x_dup(s_x, xb, r + 1, tid);
        {
            const float* srow = sp_src0 + r * WW;
#pragma unroll
            for (int m = 0; m < 24; m++) {
                sp_dst[144 * m + 2 * (m / 6)] = srow[8 * m];
            }
        }
        __syncthreads();

        int sm1 = (r + 2) % 3;
        int sm0 = r % 3;
        int sp1 = (r + 1) % 3;
        const float* xr0 = s_x + xoff + sm1 * XSLOT;
        const float* xr1 = s_x + xoff + sm0 * XSLOT;
        const float* xr2 = s_x + xoff + sp1 * XSLOT;

        u64t m0 = *(const u64t*)(xr0);
        u64t m1 = *(const u64t*)(xr1);
        u64t m2 = *(const u64t*)(xr2);
        u64t c0 = *(const u64t*)(xr0 + 2);
        u64t c1 = *(const u64t*)(xr1 + 2);
        u64t c2 = *(const u64t*)(xr2 + 2);
        const float* snp = s_spT + spoff;

#pragma unroll 4
        for (int cc = 0; cc < 48; cc++) {
            u64t p0 = *(const u64t*)(xr0 + 2 * (cc + 2));
            u64t p1 = *(const u64t*)(xr1 + 2 * (cc + 2));
            u64t p2 = *(const u64t*)(xr2 + 2 * (cc + 2));
            u64t snA = *(const u64t*)(snp);
            u64t snB = *(const u64t*)(snp + 2);

            acc[0][0] = ffma2(snA, m0, acc[0][0]);
            acc[0][1] = ffma2(snA, c0, acc[0][1]);
            acc[0][2] = ffma2(snA, p0, acc[0][2]);
            acc[0][3] = ffma2(snA, m1, acc[0][3]);
            acc[0][4] = ffma2(snA, c1, acc[0][4]);
            acc[0][5] = ffma2(snA, p1, acc[0][5]);
            acc[0][6] = ffma2(snA, m2, acc[0][6]);
            acc[0][7] = ffma2(snA, c2, acc[0][7]);
            acc[0][8] = ffma2(snA, p2, acc[0][8]);

            acc[1][0] = ffma2(snB, m0, acc[1][0]);
            acc[1][1] = ffma2(snB, c0, acc[1][1]);
            acc[1][2] = ffma2(snB, p0, acc[1][2]);
            acc[1][3] = ffma2(snB, m1, acc[1][3]);
            acc[1][4] = ffma2(snB, c1, acc[1][4]);
            acc[1][5] = ffma2(snB, p1, acc[1][5]);
            acc[1][6] = ffma2(snB, m2, acc[1][6]);
            acc[1][7] = ffma2(snB, c2, acc[1][7]);
            acc[1][8] = ffma2(snB, p2, acc[1][8]);

            m0 = c0; c0 = p0;
            m1 = c1; c1 = p1;
            m2 = c2; c2 = p2;
            snp += SPCOLSTRIDE;
        }
    }

    int cp = cgrp * 8 + cpl;
#pragma unroll
    for (int scp = 0; scp < 2; scp++) {
        int sc0 = scb + scp * 2;
        int sc1 = sc0 + 1;
        int sA = sc0 & 7, cA = sc0 >> 3;
        int sB = sc1 & 7, cB = sc1 >> 3;
        float* dA = &g_P[(((b * 8 + sA) * 2 + cA) * 64 + cp) * 9];
        float* dB = &g_P[(((b * 8 + sB) * 2 + cB) * 64 + cp) * 9];
#pragma unroll
        for (int k = 0; k < 9; k++) {
            float2 v = unpack2(acc[scp][k]);
            atomicAdd(&dA[k], v.x);
            atomicAdd(&dB[k], v.y);
        }
    }
}

// ---------------- kernel 3a: tok[b][c][d] (parallel, deep MLP) ----------------
__global__ __launch_bounds__(256) void k_tok(const float* __restrict__ Wx,
                                             const float* __restrict__ Wcs) {
    __shared__ float s_part[4][64];
    int s = blockIdx.x, c = blockIdx.y, b = blockIdx.z;
    int tid = threadIdx.x;
    int d = tid & 63;
    int q = tid >> 6;            // 0..3

    const float4* row = (const float4*)(Wx + (s * CH + d) * 576) + q * 36;
    const float4* pp = (const float4*)(g_P + (((b * NSP + s) * NCLS + c) * CH) * 9) + q * 36;
    float dot = 0.f;
#pragma unroll
    for (int m = 0; m < 36; m++) {
        float4 wv = row[m];
        float4 pv = pp[m];
        dot += wv.x * pv.x + wv.y * pv.y + wv.z * pv.z + wv.w * pv.w;
    }
    s_part[q][d] = dot;
    __syncthreads();
    if (tid < 64) {
        float inv = Wcs[s] / g_S[(b * NCLS + c) * NSP + s];
        float t = s_part[0][tid] + s_part[1][tid] + s_part[2][tid] + s_part[3][tid];
        atomicAdd(&g_tok[(b * NCLS + c) * CH + tid], inv * t);
    }
}

// ---------------- kernel 3b: U[b][c][k][o] ----------------
__global__ __launch_bounds__(576) void k_U() {
    __shared__ float s_tok[64];
    int c = blockIdx.x, b = blockIdx.y;
    int tid = threadIdx.x;
    if (tid < 64) s_tok[tid] = g_tok[(b * NCLS + c) * CH + tid];
    __syncthreads();
    int k = tid >> 6;            // 0..8
    int o = tid & 63;
    float a = 0.f;
#pragma unroll 16
    for (int dd = 0; dd < 64; dd++)
        a += g_wT[dd * 576 + k * 64 + o] * s_tok[dd];
    g_U[((b * 2 + c) * 9 + k) * 64 + o] = a;
}

// ---------------- shared tile-conv helper ----------------
__device__ __forceinline__ void conv_tile(const float s_g[2][10][19],
                                          const float s_U[2][9][64],
                                          int tid, float acc[4][8]) {
    int og = tid >> 4, pg = tid & 15;
    int row = pg >> 1, colb = (pg & 1) * 8;
    int o0 = og * 4;
#pragma unroll
    for (int oo = 0; oo < 4; oo++)
#pragma unroll
        for (int jj = 0; jj < 8; jj++) acc[oo][jj] = 0.f;
#pragma unroll
    for (int c = 0; c < 2; c++) {
#pragma unroll
        for (int ky = 0; ky < 3; ky++) {
            const float* vrow = &s_g[c][row + ky][colb];
            float v[10];
#pragma unroll
            for (int i = 0; i < 10; i++) v[i] = vrow[i];
#pragma unroll
            for (int kx = 0; kx < 3; kx++) {
                float4 wv = *(const float4*)&s_U[c][ky * 3 + kx][o0];
#pragma unroll
                for (int jj = 0; jj < 8; jj++) {
                    float vv = v[jj + kx];
                    acc[0][jj] += wv.x * vv;
                    acc[1][jj] += wv.y * vv;
                    acc[2][jj] += wv.z * vv;
                    acc[3][jj] += wv.w * vv;
                }
            }
        }
    }
}

__device__ __forceinline__ void load_gU_tiles(float s_g[2][10][19], float s_U[2][9][64],
                                              int b, int th0, int tw0, int tid) {
    {
        float4* dst = (float4*)s_U;
        const float4* src = (const float4*)(g_U + b * 1152);
        for (int i = tid; i < 288; i += 256) dst[i] = src[i];
    }
    if (tid < 180) {
        int r = tid / 18, c2 = tid % 18;
        int gh = th0 + r - 1, gw = tw0 + c2 - 1;
        float v0 = 0.f, v1 = 0.f;
        if (gh >= 0 && gh < HH && gw >= 0 && gw < WW) {
            v0 = g_g[(b * NCLS + 0) * HWSZ + gh * WW + gw];
            v1 = g_g[(b * NCLS + 1) * HWSZ + gh * WW + gw];
        }
        s_g[0][r][c2] = v0;
        s_g[1][r][c2] = v1;
    }
}

// ---------------- kernel 4: BN statistics pass ----------------
__global__ __launch_bounds__(256) void k_bnstats() {
    __shared__ float s_g[2][10][19];
    __shared__ float s_U[2][9][64];
    int b = blockIdx.z;
    int th0 = blockIdx.y * 8, tw0 = blockIdx.x * 16;
    int tid = threadIdx.x;
    load_gU_tiles(s_g, s_U, b, th0, tw0, tid);
    __syncthreads();

    float acc[4][8];
    conv_tile(s_g, s_U, tid, acc);

    int og = tid >> 4;
    int o0 = og * 4;
#pragma unroll
    for (int oo = 0; oo < 4; oo++) {
        int o = o0 + oo;
        float ss = 0.f, s2 = 0.f;
#pragma unroll
        for (int jj = 0; jj < 8; jj++) {
            ss += acc[oo][jj];
            s2 += acc[oo][jj] * acc[oo][jj];
        }
#pragma unroll
        for (int off = 8; off; off >>= 1) {
            ss += __shfl_down_sync(0xffffffffu, ss, off, 16);
            s2 += __shfl_down_sync(0xffffffffu, s2, off, 16);
        }
        if ((tid & 15) == 0) {
            atomicAdd(&g_bnsum[o], ss);
            atomicAdd(&g_bnsq[o], s2);
        }
    }
}

// ---------------- kernel 5: recompute conv, fuse BNfin+BN+ReLU+residual ----------------
__global__ __launch_bounds__(256) void k_final(const float* __restrict__ x,
                                               const float* __restrict__ gamma,
                                               const float* __restrict__ beta,
                                               float* __restrict__ out) {
    __shared__ float s_g[2][10][19];
    __shared__ float s_U[2][9][64];
    __shared__ float s_a[64], s_b[64];
    int b = blockIdx.z;
    int th0 = blockIdx.y * 8, tw0 = blockIdx.x * 16;
    int tid = threadIdx.x;
    load_gU_tiles(s_g, s_U, b, th0, tw0, tid);
    if (tid >= 192 && tid < 256) {
        int o = tid - 192;
        const float nInv = 1.0f / (float)(BB * HWSZ);
        float mean = g_bnsum[o] * nInv;
        float var = g_bnsq[o] * nInv - mean * mean;
        float a = gamma[o] * rsqrtf(var + 1e-5f);
        s_a[o] = a;
        s_b[o] = beta[o] - mean * a;
    }
    __syncthreads();

    float acc[4][8];
    conv_tile(s_g, s_U, tid, acc);

    int og = tid >> 4, pg = tid & 15;
    int row = pg >> 1, colb = (pg & 1) * 8;
    int o0 = og * 4;
#pragma unroll
    for (int oo = 0; oo < 4; oo++) {
        int o = o0 + oo;
        float a = s_a[o], bb = s_b[o];
        size_t off = (((size_t)b * CH + o) * HH + th0 + row) * WW + tw0 + colb;
        const float4 xlo = *(const float4*)(x + off);
        const float4 xhi = *(const float4*)(x + off + 4);
        float4 rlo, rhi;
        rlo.x = xlo.x + fmaxf(acc[oo][0] * a + bb, 0.f);
        rlo.y = xlo.y + fmaxf(acc[oo][1] * a + bb, 0.f);
        rlo.z = xlo.z + fmaxf(acc[oo][2] * a + bb, 0.f);
        rlo.w = xlo.w + fmaxf(acc[oo][3] * a + bb, 0.f);
        rhi.x = xhi.x + fmaxf(acc[oo][4] * a + bb, 0.f);
        rhi.y = xhi.y + fmaxf(acc[oo][5] * a + bb, 0.f);
        rhi.z = xhi.z + fmaxf(acc[oo][6] * a + bb, 0.f);
        rhi.w = xhi.w + fmaxf(acc[oo][7] * a + bb, 0.f);
        *(float4*)(out + off) = rlo;
        *(float4*)(out + off + 4) = rhi;
    }
}

// ---------------- launch ----------------
extern "C" void kernel_launch(void* const* d_in, const int* in_sizes, int n_in,
                              void* d_out, int out_size) {
    const float* x      = (const float*)d_in[0];
    const float* cs     = (const float*)d_in[1];
    const float* Wcsp   = (const float*)d_in[2];
    const float* Wx     = (const float*)d_in[3];
    const float* Wcs    = (const float*)d_in[4];
    const float* Wcv    = (const float*)d_in[5];
    const float* Wa     = (const float*)d_in[6];
    const float* Wcomb  = (const float*)d_in[7];
    const float* Wsing  = (const float*)d_in[8];
    const float* gamma  = (const float*)d_in[9];
    const float* beta   = (const float*)d_in[10];
    float* out = (float*)d_out;

    k_zero<<<288, 256>>>();
    k_wT<<<144, 256>>>(Wsing);
    k_spaceg<<<dim3(48, 8), 256>>>(cs, Wcsp, Wcv, Wa, Wcomb);
    k_P<<<dim3(16, 8, 8), 128>>>(x);
    k_tok<<<dim3(8, 2, 8), 256>>>(Wx, Wcs);
    k_U<<<dim3(2, 8), 576>>>();
    k_bnstats<<<dim3(12, 24, 8), 256>>>();
    k_final<<<dim3(12, 24, 8), 256>>>(x, gamma, beta, out);
}